// round 12
// baseline (speedup 1.0000x reference)
#include <cuda_runtime.h>
#include <cuda_bf16.h>

typedef unsigned long long ull;

// ---------------- packed f32x2 helpers (sm_103a) ----------------
__device__ __forceinline__ ull pk2(float a, float b){
    ull r; asm("mov.b64 %0,{%1,%2};" : "=l"(r) : "f"(a), "f"(b)); return r;
}
__device__ __forceinline__ void upk2(ull v, float& a, float& b){
    asm("mov.b64 {%0,%1},%2;" : "=f"(a), "=f"(b) : "l"(v));
}
__device__ __forceinline__ ull mul2(ull a, ull b){
    ull r; asm("mul.rn.f32x2 %0,%1,%2;" : "=l"(r) : "l"(a), "l"(b)); return r;
}
__device__ __forceinline__ void fma2(ull& d, ull a, ull b){
    asm("fma.rn.f32x2 %0,%1,%2,%0;" : "+l"(d) : "l"(a), "l"(b));
}
__device__ __forceinline__ void lds2u64(unsigned a, ull& x, ull& y){
    asm volatile("ld.shared.v2.b64 {%0,%1},[%2];" : "=l"(x), "=l"(y) : "r"(a));
}
__device__ __forceinline__ void lds1u64(unsigned a, ull& x){
    asm volatile("ld.shared.b64 %0,[%1];" : "=l"(x) : "r"(a));
}
__device__ __forceinline__ void sts2u64(unsigned a, ull x, ull y){
    asm volatile("st.shared.v2.b64 [%0],{%1,%2};" :: "r"(a), "l"(x), "l"(y));
}
__device__ __forceinline__ void sts1u64(unsigned a, ull x){
    asm volatile("st.shared.b64 [%0],%1;" :: "r"(a), "l"(x));
}

// Tile: 4 rows x 32 cols x all 64 channels. 512 threads = 16 warps.
// smem (float offsets):
//   xs  [0     .. 15616)  halo: xs[c][r][s] = c*244 + r*40 + s  (6 rows, s=3..36)
//   Hs  [15616 .. 32000)  dup h pairs: ull at o*128 + px   (64 KB)
//        (reused at end as res[c*133 + px] transpose buffer)
//   w2q [32000 .. 41504)  chunk weights: ull at (oc*9+k)*33 + cp  (cp padded to 33)
//   w1d [41504 .. 49696)  packed dup w1: [cc][g][w16] 16B chunks (8192 floats)
#define XS_STRIDE 244
#define HS_OFF   15616
#define W2P_OFF  32000
#define W1D_OFF  41504
#define SMEM_FLOATS 49696
#define SMEM_BYTES  (SMEM_FLOATS*4)

// 9-tap sum for one pixel: rows T[R0..R2], col window starting at J
#define TAPSUM(t, R0, R1, R2, J) \
    t = mul2(w0_, T[R0][J]);   fma2(t, w1_, T[R0][(J)+1]); fma2(t, w2_, T[R0][(J)+2]); \
    fma2(t, w3_, T[R1][J]);    fma2(t, w4_, T[R1][(J)+1]); fma2(t, w5_, T[R1][(J)+2]); \
    fma2(t, w6_, T[R2][J]);    fma2(t, w7_, T[R2][(J)+1]); fma2(t, w8_, T[R2][(J)+2]);

__global__ void __launch_bounds__(512, 1)
invol_kernel(const float* __restrict__ x, const float* __restrict__ w1,
             const float* __restrict__ w2, float* __restrict__ out)
{
    extern __shared__ float sm[];
    const unsigned su = (unsigned)__cvta_generic_to_shared(sm);

    const int tid = threadIdx.x;
    const int L   = tid & 31;
    const int wid = tid >> 5;
    const int w0c = blockIdx.x * 32;
    const int h0  = blockIdx.y * 4;
    const int b   = blockIdx.z;

    const float* xb = x + (size_t)b * 64 * 224 * 224;

    // ---------------- Stage A: 64c x 6r x 34col halo into xs ----------------
    for (int row = wid; row < 384; row += 16) {
        int c = row / 6, r = row - 6 * c;
        int gr = h0 - 1 + r;
        bool rok = ((unsigned)gr < 224u);
        const float* src = xb + ((size_t)c * 224 + gr) * 224;
        float* dst = sm + c * XS_STRIDE + r * 40 + 3;
        #pragma unroll
        for (int ii = 0; ii < 2; ++ii) {
            int i = L + 32 * ii;
            if (i < 34) {
                int g = w0c - 1 + i;
                dst[i] = (rok && (unsigned)g < 224u) ? __ldg(src + g) : 0.0f;
            }
        }
    }

    // ---------------- Stage W1d: pack duplicated w1 pairs -------------------
    #pragma unroll
    for (int t = 0; t < 4; ++t) {
        int u = tid + 512 * t;
        int w16 = u & 15;
        int g   = (u >> 4) & 1;
        int cc  = u >> 5;
        int o0 = w16 + 32 * g, o1 = o0 + 16;
        float a = __ldg(w1 + o0 * 64 + cc);
        float c2 = __ldg(w1 + o1 * 64 + cc);
        sts2u64(su + (W1D_OFF + cc * 128 + g * 64 + w16 * 4) * 4,
                pk2(a, a), pk2(c2, c2));
    }
    __syncthreads();

    // ---------------- Stage B: h[o,p] = relu(sum_c w1[o,c]*x[c,p]) ----------
    {
        const int ro = L >> 3;
        const int cb = (L & 7) * 4;
        const unsigned xrow   = su + ((ro + 1) * 40 + 4 + cb) * 4;   // + c*976
        const unsigned w1base = su + W1D_OFF * 4 + wid * 16;
        ull hA[4], hB[4];
        #pragma unroll
        for (int oi = 0; oi < 4; ++oi) { hA[oi] = 0ull; hB[oi] = 0ull; }

        #pragma unroll 8
        for (int cc = 0; cc < 64; ++cc) {
            ull xA, xB;   lds2u64(xrow + cc * (XS_STRIDE*4), xA, xB);
            ull wA0, wA1; lds2u64(w1base + cc * 512, wA0, wA1);
            ull wB0, wB1; lds2u64(w1base + cc * 512 + 256, wB0, wB1);
            fma2(hA[0], wA0, xA); fma2(hB[0], wA0, xB);
            fma2(hA[1], wA1, xA); fma2(hB[1], wA1, xB);
            fma2(hA[2], wB0, xA); fma2(hB[2], wB0, xB);
            fma2(hA[3], wB1, xA); fma2(hB[3], wB1, xB);
        }
        const unsigned HSb = su + HS_OFF * 4;
        #pragma unroll
        for (int oi = 0; oi < 4; ++oi) {
            int o = wid + 16 * oi;
            float a0, a1, a2, a3;
            upk2(hA[oi], a0, a1); upk2(hB[oi], a2, a3);
            a0 = fmaxf(a0, 0.0f); a1 = fmaxf(a1, 0.0f);
            a2 = fmaxf(a2, 0.0f); a3 = fmaxf(a3, 0.0f);
            unsigned base = HSb + (o * 128 + ro * 32 + cb) * 8;
            sts2u64(base,      pk2(a0, a0), pk2(a1, a1));
            sts2u64(base + 16, pk2(a2, a2), pk2(a3, a3));
        }
    }

    // ---------------- Stage C -----------------------------------------------
    // warp -> 2 rows x 4 cols of pixels; lane -> channel pair (2L, 2L+1)
    const int rp  = (wid & 1) * 2;
    const int cwb = (wid >> 1) * 4;

    // tap pairs: T[i][m] = (x[c0, halo row rp+i, tap col m], x[c1, ...])
    // pixel j's taps live at halo offsets 3+j, 4+j, 5+j  (j = cwb+dq)
    ull T[4][6];
    #pragma unroll
    for (int i = 0; i < 4; ++i) {
        const float* pr0 = sm + (2 * L) * XS_STRIDE + (rp + i) * 40 + 3 + cwb;
        const float* pr1 = pr0 + XS_STRIDE;
        #pragma unroll
        for (int m = 0; m < 6; ++m) T[i][m] = pk2(pr0[m], pr1[m]);
    }

    ull acc[2][4];
    #pragma unroll
    for (int dr = 0; dr < 2; ++dr)
        #pragma unroll
        for (int dq = 0; dq < 4; ++dq) acc[dr][dq] = 0ull;

    const unsigned HSb  = su + HS_OFF * 4;
    const unsigned W2Pb = su + W2P_OFF * 4;

    #pragma unroll 1
    for (int och = 0; och < 4; ++och) {
        if (och) __syncthreads();         // prev chunk reads complete
        // stage w2 chunk: 4608 real ull = (16 oc) x (9 k) x (32 cp), cp padded to 33
        // store addr: ((oc*9+k)*33 + cp) * 8 ; global reads oc-coalesced
        #pragma unroll
        for (int t = 0; t < 9; ++t) {
            int u = tid + 512 * t;        // 0..4607
            int oc = u & 15;
            int rest = u >> 4;            // 0..287
            int cp = rest / 9;
            int k  = rest - cp * 9;
            const float* p = w2 + (size_t)(cp * 18 + k) * 64 + (och * 16 + oc);
            float v0 = __ldg(p);
            float v1 = __ldg(p + 576);    // channel 2cp+1 -> +9*64
            sts1u64(W2Pb + (unsigned)((oc * 9 + k) * 33 + cp) * 8, pk2(v0, v1));
        }
        __syncthreads();                  // chunk staged (och=0: also Hs ready)

        unsigned hb = HSb + ((och * 16) * 128 + rp * 32 + cwb) * 8;
        unsigned wq = W2Pb + L * 8;       // lane = cp; k stride 33*8=264B, oc stride 2376B

        #pragma unroll 1
        for (int oc = 0; oc < 16; ++oc) {
            ull w0_, w1_, w2_, w3_, w4_, w5_, w6_, w7_, w8_;
            lds1u64(wq +    0, w0_);
            lds1u64(wq +  264, w1_);
            lds1u64(wq +  528, w2_);
            lds1u64(wq +  792, w3_);
            lds1u64(wq + 1056, w4_);
            lds1u64(wq + 1320, w5_);
            lds1u64(wq + 1584, w6_);
            lds1u64(wq + 1848, w7_);
            lds1u64(wq + 2112, w8_);
            wq += 2376;
            ull hA0, hA1, hA2, hA3, hB0, hB1, hB2, hB3;
            lds2u64(hb,            hA0, hA1);
            lds2u64(hb + 16,       hA2, hA3);
            lds2u64(hb + 256,      hB0, hB1);
            lds2u64(hb + 256 + 16, hB2, hB3);
            hb += 1024;

            ull t;
            TAPSUM(t, 0, 1, 2, 0); fma2(acc[0][0], hA0, t);
            TAPSUM(t, 0, 1, 2, 1); fma2(acc[0][1], hA1, t);
            TAPSUM(t, 0, 1, 2, 2); fma2(acc[0][2], hA2, t);
            TAPSUM(t, 0, 1, 2, 3); fma2(acc[0][3], hA3, t);
            TAPSUM(t, 1, 2, 3, 0); fma2(acc[1][0], hB0, t);
            TAPSUM(t, 1, 2, 3, 1); fma2(acc[1][1], hB1, t);
            TAPSUM(t, 1, 2, 3, 2); fma2(acc[1][2], hB2, t);
            TAPSUM(t, 1, 2, 3, 3); fma2(acc[1][3], hB3, t);
        }
    }

    // ---------------- Output: transpose through smem, coalesced store -------
    __syncthreads();                      // all Hs reads done before overwrite
    #pragma unroll
    for (int dr = 0; dr < 2; ++dr)
        #pragma unroll
        for (int dq = 0; dq < 4; ++dq) {
            float lo, hi; upk2(acc[dr][dq], lo, hi);
            int px = (rp + dr) * 32 + cwb + dq;
            sm[HS_OFF + (2 * L) * 133 + px]     = lo;
            sm[HS_OFF + (2 * L + 1) * 133 + px] = hi;
        }
    __syncthreads();
    {
        int seg  = tid >> 1;              // 0..255 = (c, row)
        int c    = seg >> 2;
        int row  = seg & 3;
        int colb = (tid & 1) * 16;
        const float* rsrc = sm + HS_OFF + c * 133 + row * 32 + colb;
        float* og = out + (((size_t)(b * 64 + c) * 224) + (h0 + row)) * 224
                        + w0c + colb;
        #pragma unroll
        for (int j = 0; j < 4; ++j) {
            float4 v;
            v.x = rsrc[4 * j];     v.y = rsrc[4 * j + 1];
            v.z = rsrc[4 * j + 2]; v.w = rsrc[4 * j + 3];
            *(float4*)(og + 4 * j) = v;
        }
    }
}

extern "C" void kernel_launch(void* const* d_in, const int* in_sizes, int n_in,
                              void* d_out, int out_size)
{
    const float* x  = (const float*)d_in[0];   // (4,64,224,224)
    const float* w1 = (const float*)d_in[1];   // (64,64)
    const float* w2 = (const float*)d_in[2];   // (576,64)
    float* out = (float*)d_out;                // (4,64,224,224)

    cudaFuncSetAttribute(invol_kernel,
                         cudaFuncAttributeMaxDynamicSharedMemorySize, SMEM_BYTES);
    dim3 grid(224 / 32, 224 / 4, 4);           // 7 x 56 x 4 = 1568 blocks
    invol_kernel<<<grid, 512, SMEM_BYTES>>>(x, w1, w2, out);
}

// round 13
// speedup vs baseline: 1.0218x; 1.0218x over previous
#include <cuda_runtime.h>
#include <cuda_bf16.h>

typedef unsigned long long ull;

// ---------------- packed f32x2 helpers (sm_103a) ----------------
__device__ __forceinline__ ull pk2(float a, float b){
    ull r; asm("mov.b64 %0,{%1,%2};" : "=l"(r) : "f"(a), "f"(b)); return r;
}
__device__ __forceinline__ void upk2(ull v, float& a, float& b){
    asm("mov.b64 {%0,%1},%2;" : "=f"(a), "=f"(b) : "l"(v));
}
__device__ __forceinline__ ull mul2(ull a, ull b){
    ull r; asm("mul.rn.f32x2 %0,%1,%2;" : "=l"(r) : "l"(a), "l"(b)); return r;
}
__device__ __forceinline__ void fma2(ull& d, ull a, ull b){
    asm("fma.rn.f32x2 %0,%1,%2,%0;" : "+l"(d) : "l"(a), "l"(b));
}
__device__ __forceinline__ void lds2u64(unsigned a, ull& x, ull& y){
    asm volatile("ld.shared.v2.b64 {%0,%1},[%2];" : "=l"(x), "=l"(y) : "r"(a));
}
__device__ __forceinline__ void lds1u64(unsigned a, ull& x){
    asm volatile("ld.shared.b64 %0,[%1];" : "=l"(x) : "r"(a));
}
__device__ __forceinline__ void sts2u64(unsigned a, ull x, ull y){
    asm volatile("st.shared.v2.b64 [%0],{%1,%2};" :: "r"(a), "l"(x), "l"(y));
}
__device__ __forceinline__ void sts1u64(unsigned a, ull x){
    asm volatile("st.shared.b64 [%0],%1;" :: "r"(a), "l"(x));
}

// Tile: 4 rows x 32 cols x all 64 channels. 512 threads = 16 warps.
// smem (float offsets):
//   xs  [0     .. 15616)  halo: xs[c][r][s] = c*244 + r*40 + s  (6 rows, s=3..36)
//   Hs  [15616 .. 32000)  dup h pairs: ull at o*128 + px   (64 KB)
//        (reused at end as res[c*133 + px] transpose buffer)
//   w2q [32000 .. 41504)  chunk weights: ull at (oc*9+k)*33 + cp  (cp padded to 33)
//   w1d [41504 .. 49696)  packed dup w1: [cc][g][w16] 16B chunks (8192 floats)
#define XS_STRIDE 244
#define HS_OFF   15616
#define W2P_OFF  32000
#define W1D_OFF  41504
#define SMEM_FLOATS 49696
#define SMEM_BYTES  (SMEM_FLOATS*4)

// 9-tap sum for one pixel: rows T[R0..R2], col window starting at J
#define TAPSUM(t, R0, R1, R2, J) \
    t = mul2(w0_, T[R0][J]);   fma2(t, w1_, T[R0][(J)+1]); fma2(t, w2_, T[R0][(J)+2]); \
    fma2(t, w3_, T[R1][J]);    fma2(t, w4_, T[R1][(J)+1]); fma2(t, w5_, T[R1][(J)+2]); \
    fma2(t, w6_, T[R2][J]);    fma2(t, w7_, T[R2][(J)+1]); fma2(t, w8_, T[R2][(J)+2]);

__global__ void __launch_bounds__(512, 1)
invol_kernel(const float* __restrict__ x, const float* __restrict__ w1,
             const float* __restrict__ w2, float* __restrict__ out)
{
    extern __shared__ float sm[];
    const unsigned su = (unsigned)__cvta_generic_to_shared(sm);

    const int tid = threadIdx.x;
    const int L   = tid & 31;
    const int wid = tid >> 5;
    const int w0c = blockIdx.x * 32;
    const int h0  = blockIdx.y * 4;
    const int b   = blockIdx.z;

    const float* xb = x + (size_t)b * 64 * 224 * 224;

    // ---------------- Stage A: 64c x 6r x 34col halo into xs ----------------
    for (int row = wid; row < 384; row += 16) {
        int c = row / 6, r = row - 6 * c;
        int gr = h0 - 1 + r;
        bool rok = ((unsigned)gr < 224u);
        const float* src = xb + ((size_t)c * 224 + gr) * 224;
        float* dst = sm + c * XS_STRIDE + r * 40 + 3;
        #pragma unroll
        for (int ii = 0; ii < 2; ++ii) {
            int i = L + 32 * ii;
            if (i < 34) {
                int g = w0c - 1 + i;
                dst[i] = (rok && (unsigned)g < 224u) ? __ldg(src + g) : 0.0f;
            }
        }
    }

    // ---------------- Stage W1d: pack duplicated w1 pairs -------------------
    #pragma unroll
    for (int t = 0; t < 4; ++t) {
        int u = tid + 512 * t;
        int w16 = u & 15;
        int g   = (u >> 4) & 1;
        int cc  = u >> 5;
        int o0 = w16 + 32 * g, o1 = o0 + 16;
        float a = __ldg(w1 + o0 * 64 + cc);
        float c2 = __ldg(w1 + o1 * 64 + cc);
        sts2u64(su + (W1D_OFF + cc * 128 + g * 64 + w16 * 4) * 4,
                pk2(a, a), pk2(c2, c2));
    }
    __syncthreads();

    // ---------------- Stage B: h[o,p] = relu(sum_c w1[o,c]*x[c,p]) ----------
    {
        const int ro = L >> 3;
        const int cb = (L & 7) * 4;
        const unsigned xrow   = su + ((ro + 1) * 40 + 4 + cb) * 4;   // + c*976
        const unsigned w1base = su + W1D_OFF * 4 + wid * 16;
        ull hA[4], hB[4];
        #pragma unroll
        for (int oi = 0; oi < 4; ++oi) { hA[oi] = 0ull; hB[oi] = 0ull; }

        #pragma unroll 8
        for (int cc = 0; cc < 64; ++cc) {
            ull xA, xB;   lds2u64(xrow + cc * (XS_STRIDE*4), xA, xB);
            ull wA0, wA1; lds2u64(w1base + cc * 512, wA0, wA1);
            ull wB0, wB1; lds2u64(w1base + cc * 512 + 256, wB0, wB1);
            fma2(hA[0], wA0, xA); fma2(hB[0], wA0, xB);
            fma2(hA[1], wA1, xA); fma2(hB[1], wA1, xB);
            fma2(hA[2], wB0, xA); fma2(hB[2], wB0, xB);
            fma2(hA[3], wB1, xA); fma2(hB[3], wB1, xB);
        }
        const unsigned HSb = su + HS_OFF * 4;
        #pragma unroll
        for (int oi = 0; oi < 4; ++oi) {
            int o = wid + 16 * oi;
            float a0, a1, a2, a3;
            upk2(hA[oi], a0, a1); upk2(hB[oi], a2, a3);
            a0 = fmaxf(a0, 0.0f); a1 = fmaxf(a1, 0.0f);
            a2 = fmaxf(a2, 0.0f); a3 = fmaxf(a3, 0.0f);
            unsigned base = HSb + (o * 128 + ro * 32 + cb) * 8;
            sts2u64(base,      pk2(a0, a0), pk2(a1, a1));
            sts2u64(base + 16, pk2(a2, a2), pk2(a3, a3));
        }
    }

    // ---------------- Stage C -----------------------------------------------
    // warp -> 2 rows x 4 cols of pixels; lane -> channel pair (2L, 2L+1)
    const int rp  = (wid & 1) * 2;
    const int cwb = (wid >> 1) * 4;

    // tap pairs: T[i][m] = (x[c0, halo row rp+i, tap col m], x[c1, ...])
    // pixel j's taps live at halo offsets 3+j, 4+j, 5+j  (j = cwb+dq)
    ull T[4][6];
    #pragma unroll
    for (int i = 0; i < 4; ++i) {
        const float* pr0 = sm + (2 * L) * XS_STRIDE + (rp + i) * 40 + 3 + cwb;
        const float* pr1 = pr0 + XS_STRIDE;
        #pragma unroll
        for (int m = 0; m < 6; ++m) T[i][m] = pk2(pr0[m], pr1[m]);
    }

    ull acc[2][4];
    #pragma unroll
    for (int dr = 0; dr < 2; ++dr)
        #pragma unroll
        for (int dq = 0; dq < 4; ++dq) acc[dr][dq] = 0ull;

    const unsigned HSb  = su + HS_OFF * 4;
    const unsigned W2Pb = su + W2P_OFF * 4;

    #pragma unroll 1
    for (int och = 0; och < 4; ++och) {
        if (och) __syncthreads();         // prev chunk reads complete
        // stage w2 chunk: 4608 real ull = (16 oc) x (9 k) x (32 cp), cp padded to 33
        // store addr: ((oc*9+k)*33 + cp) * 8 ; global reads oc-coalesced
        #pragma unroll
        for (int t = 0; t < 9; ++t) {
            int u = tid + 512 * t;        // 0..4607
            int oc = u & 15;
            int rest = u >> 4;            // 0..287
            int cp = rest / 9;
            int k  = rest - cp * 9;
            const float* p = w2 + (size_t)(cp * 18 + k) * 64 + (och * 16 + oc);
            float v0 = __ldg(p);
            float v1 = __ldg(p + 576);    // channel 2cp+1 -> +9*64
            sts1u64(W2Pb + (unsigned)((oc * 9 + k) * 33 + cp) * 8, pk2(v0, v1));
        }
        __syncthreads();                  // chunk staged (och=0: also Hs ready)

        // Convoy-breaking rotation: each warp walks the 16 ocs of this chunk
        // starting at a different offset, so warps on one SMSP are in
        // different load/compute phases and cover each other's LDS latency.
        #pragma unroll 1
        for (int ii = 0; ii < 16; ++ii) {
            const int oce = (ii + wid) & 15;
            unsigned wq = W2Pb + (unsigned)L * 8 + (unsigned)(oce * 2376);
            unsigned hb = HSb + (unsigned)(((och * 16 + oce) * 128
                                            + rp * 32 + cwb) * 8);

            // h loads first (consumed last -> max slack)
            ull hA0, hA1, hA2, hA3, hB0, hB1, hB2, hB3;
            lds2u64(hb,            hA0, hA1);
            lds2u64(hb + 16,       hA2, hA3);
            lds2u64(hb + 256,      hB0, hB1);
            lds2u64(hb + 256 + 16, hB2, hB3);

            ull w0_, w1_, w2_, w3_, w4_, w5_, w6_, w7_, w8_;
            lds1u64(wq +    0, w0_);
            lds1u64(wq +  264, w1_);
            lds1u64(wq +  528, w2_);
            lds1u64(wq +  792, w3_);
            lds1u64(wq + 1056, w4_);
            lds1u64(wq + 1320, w5_);
            lds1u64(wq + 1584, w6_);
            lds1u64(wq + 1848, w7_);
            lds1u64(wq + 2112, w8_);

            ull t;
            TAPSUM(t, 0, 1, 2, 0); fma2(acc[0][0], hA0, t);
            TAPSUM(t, 0, 1, 2, 1); fma2(acc[0][1], hA1, t);
            TAPSUM(t, 0, 1, 2, 2); fma2(acc[0][2], hA2, t);
            TAPSUM(t, 0, 1, 2, 3); fma2(acc[0][3], hA3, t);
            TAPSUM(t, 1, 2, 3, 0); fma2(acc[1][0], hB0, t);
            TAPSUM(t, 1, 2, 3, 1); fma2(acc[1][1], hB1, t);
            TAPSUM(t, 1, 2, 3, 2); fma2(acc[1][2], hB2, t);
            TAPSUM(t, 1, 2, 3, 3); fma2(acc[1][3], hB3, t);
        }
    }

    // ---------------- Output: transpose through smem, coalesced store -------
    __syncthreads();                      // all Hs reads done before overwrite
    #pragma unroll
    for (int dr = 0; dr < 2; ++dr)
        #pragma unroll
        for (int dq = 0; dq < 4; ++dq) {
            float lo, hi; upk2(acc[dr][dq], lo, hi);
            int px = (rp + dr) * 32 + cwb + dq;
            sm[HS_OFF + (2 * L) * 133 + px]     = lo;
            sm[HS_OFF + (2 * L + 1) * 133 + px] = hi;
        }
    __syncthreads();
    {
        int seg  = tid >> 1;              // 0..255 = (c, row)
        int c    = seg >> 2;
        int row  = seg & 3;
        int colb = (tid & 1) * 16;
        const float* rsrc = sm + HS_OFF + c * 133 + row * 32 + colb;
        float* og = out + (((size_t)(b * 64 + c) * 224) + (h0 + row)) * 224
                        + w0c + colb;
        #pragma unroll
        for (int j = 0; j < 4; ++j) {
            float4 v;
            v.x = rsrc[4 * j];     v.y = rsrc[4 * j + 1];
            v.z = rsrc[4 * j + 2]; v.w = rsrc[4 * j + 3];
            *(float4*)(og + 4 * j) = v;
        }
    }
}

extern "C" void kernel_launch(void* const* d_in, const int* in_sizes, int n_in,
                              void* d_out, int out_size)
{
    const float* x  = (const float*)d_in[0];   // (4,64,224,224)
    const float* w1 = (const float*)d_in[1];   // (64,64)
    const float* w2 = (const float*)d_in[2];   // (576,64)
    float* out = (float*)d_out;                // (4,64,224,224)

    cudaFuncSetAttribute(invol_kernel,
                         cudaFuncAttributeMaxDynamicSharedMemorySize, SMEM_BYTES);
    dim3 grid(224 / 32, 224 / 4, 4);           // 7 x 56 x 4 = 1568 blocks
    invol_kernel<<<grid, 512, SMEM_BYTES>>>(x, w1, w2, out);
}

// round 16
// speedup vs baseline: 1.1234x; 1.0994x over previous
#include <cuda_runtime.h>
#include <cuda_bf16.h>
#include <cstdint>

// ---------- warp-level bf16 MMA (plain PTX, works at compute_103) ----------
__device__ __forceinline__ void mma_bf16(float* c, const uint32_t* a, const uint32_t* b){
    asm volatile("mma.sync.aligned.m16n8k16.row.col.f32.bf16.bf16.f32 "
        "{%0,%1,%2,%3},{%4,%5,%6,%7},{%8,%9},{%0,%1,%2,%3};"
        : "+f"(c[0]), "+f"(c[1]), "+f"(c[2]), "+f"(c[3])
        : "r"(a[0]), "r"(a[1]), "r"(a[2]), "r"(a[3]), "r"(b[0]), "r"(b[1]));
}
__device__ __forceinline__ void ldsm_x4(uint32_t* r, uint32_t a){
    asm volatile("ldmatrix.sync.aligned.m8n8.x4.shared.b16 {%0,%1,%2,%3},[%4];"
        : "=r"(r[0]), "=r"(r[1]), "=r"(r[2]), "=r"(r[3]) : "r"(a));
}
__device__ __forceinline__ void ldsm_x2(uint32_t* r, uint32_t a){
    asm volatile("ldmatrix.sync.aligned.m8n8.x2.shared.b16 {%0,%1},[%2];"
        : "=r"(r[0]), "=r"(r[1]) : "r"(a));
}
#define SWZ128(off) ((off) ^ (((off) >> 3) & 0x70))

// split fp32 -> bf16 hi + bf16 lo(residual), pack 2 values per b32
__device__ __forceinline__ void split_pack(float v0, float v1, uint32_t& hi, uint32_t& lo){
    __nv_bfloat16 h0 = __float2bfloat16_rn(v0), h1 = __float2bfloat16_rn(v1);
    __nv_bfloat16 l0 = __float2bfloat16_rn(v0 - __bfloat162float(h0));
    __nv_bfloat16 l1 = __float2bfloat16_rn(v1 - __bfloat162float(h1));
    hi = (uint32_t)__bfloat16_as_ushort(h0) | ((uint32_t)__bfloat16_as_ushort(h1) << 16);
    lo = (uint32_t)__bfloat16_as_ushort(l0) | ((uint32_t)__bfloat16_as_ushort(l1) << 16);
}

// ---------------- smem layout (bytes) ----------------
// xs halo 64c x 6r x 40f @1024 (61440B). K-major bf16 tiles: 128B rows, swizzled.
#define SM_XS    1024
#define SM_B2HI  62464    // 144 x 128B = 18432
#define SM_B2LO  80896
#define SM_A2HI  99328    // 128 x 128B = 16384
#define SM_A2LO  115712
#define SM_KERN  132096   // 128 px x 150 f32 (600B) = 76800
#define SM_A1HI  132096   // overlays kern (dead after stage 1)
#define SM_A1LO  148480
#define SM_B1HI  164864   // 64 x 128B = 8192
#define SM_B1LO  173056
#define SM_TOTAL 208896
#define KSTRIDE_W 150     // kern row stride in words

__global__ void __launch_bounds__(256, 1)
invol_mma_kernel(const float* __restrict__ x, const float* __restrict__ w1,
                 const float* __restrict__ w2, float* __restrict__ out)
{
    extern __shared__ float sm[];
    char* smb = (char*)sm;
    uint32_t su;
    asm("{ .reg .u64 t; cvta.to.shared.u64 t, %1; cvt.u32.u64 %0, t; }" : "=r"(su) : "l"(smb));

    const int tid = threadIdx.x;
    const int L   = tid & 31;
    const int wid = tid >> 5;           // 8 warps
    const int w0c = blockIdx.x * 32;
    const int h0  = blockIdx.y * 4;
    const int b   = blockIdx.z;

    // ---------------- halo: 64c x 6r x 34col ----------------
    const float* xb = x + (size_t)b * 64 * 224 * 224;
    for (int rr = wid; rr < 384; rr += 8) {
        int c = rr / 6, r = rr - 6 * c;
        int gr = h0 - 1 + r;
        bool rok = ((unsigned)gr < 224u);
        const float* src = xb + ((size_t)c * 224 + gr) * 224;
        float* dst = sm + 256 + c * 240 + r * 40 + 3;
        #pragma unroll
        for (int ii = 0; ii < 2; ++ii) {
            int i = L + 32 * ii;
            if (i < 34) {
                int g = w0c - 1 + i;
                dst[i] = (rok && (unsigned)g < 224u) ? __ldg(src + g) : 0.0f;
            }
        }
    }

    // ---------------- stage B1 = w1 (64 rows x 64 k) bf16 hi/lo ----------------
    #pragma unroll
    for (int t = 0; t < 8; ++t) {
        int p = tid + 256 * t;              // 2048 float2-pairs
        int row = p >> 5, kp = p & 31;
        float2 v = *(const float2*)(w1 + row * 64 + kp * 2);
        uint32_t hi, lo; split_pack(v.x, v.y, hi, lo);
        uint32_t off = SWZ128((uint32_t)(row * 128 + kp * 4));
        *(uint32_t*)(smb + SM_B1HI + off) = hi;
        *(uint32_t*)(smb + SM_B1LO + off) = lo;
    }
    __syncthreads();    // halo complete before ANY xs read (A1 staging below)

    // ---------------- A1[px][c] from halo center, bf16 hi/lo -------------------
    {
        int px = tid >> 1, ch0 = (tid & 1) * 32;
        int rp = px >> 5, col = px & 31;
        const float* base = sm + 256 + (rp + 1) * 40 + 4 + col;   // + c*240
        #pragma unroll
        for (int cc = 0; cc < 16; ++cc) {
            int c = ch0 + 2 * cc;
            float v0 = base[c * 240], v1 = base[(c + 1) * 240];
            uint32_t hi, lo; split_pack(v0, v1, hi, lo);
            uint32_t off = SWZ128((uint32_t)(px * 128 + c * 2));
            *(uint32_t*)(smb + SM_A1HI + off) = hi;
            *(uint32_t*)(smb + SM_A1LO + off) = lo;
        }
    }
    __syncthreads();

    // ---------------- per-lane ldmatrix address components ---------------------
    const int mb = wid * 16;                       // warp's m strip
    const int arow = mb + (L & 7) + ((L & 8) ? 8 : 0);
    const uint32_t aoff = (uint32_t)(arow * 128);
    const int ars = arow & 7, akh = (L >> 4) & 1;
    const int lr = L & 7, bkb = (L >> 3) & 1;
    const uint32_t boff = (uint32_t)(lr * 128);
    uint32_t aswz[4], bswz[4];
    #pragma unroll
    for (int kk = 0; kk < 4; ++kk) {
        aswz[kk] = (uint32_t)(((2 * kk + akh) ^ ars) << 4);
        bswz[kk] = (uint32_t)(((2 * kk + bkb) ^ lr) << 4);
    }
    const int g = L >> 2, q = L & 3;               // C-frag ownership

    float acc[72];

    // ================= stage 1 MMA: h = relu(X * w1^T), N=64 =================
    #pragma unroll
    for (int i = 0; i < 32; ++i) acc[i] = 0.0f;
    #pragma unroll
    for (int kk = 0; kk < 4; ++kk) {
        uint32_t Ah[4], Al[4];
        ldsm_x4(Ah, su + SM_A1HI + aoff + aswz[kk]);
        ldsm_x4(Al, su + SM_A1LO + aoff + aswz[kk]);
        #pragma unroll
        for (int nt = 0; nt < 8; ++nt) {
            uint32_t Bh[2], Bl[2];
            ldsm_x2(Bh, su + SM_B1HI + nt * 1024 + boff + bswz[kk]);
            ldsm_x2(Bl, su + SM_B1LO + nt * 1024 + boff + bswz[kk]);
            mma_bf16(acc + nt * 4, Ah, Bh);
            mma_bf16(acc + nt * 4, Al, Bh);
            mma_bf16(acc + nt * 4, Ah, Bl);
        }
    }
    // relu + split -> A2[px][o]
    #pragma unroll
    for (int nt = 0; nt < 8; ++nt) {
        int n0 = nt * 8 + q * 2;
        float v0 = fmaxf(acc[nt * 4 + 0], 0.0f), v1 = fmaxf(acc[nt * 4 + 1], 0.0f);
        float v2 = fmaxf(acc[nt * 4 + 2], 0.0f), v3 = fmaxf(acc[nt * 4 + 3], 0.0f);
        uint32_t hi, lo;
        split_pack(v0, v1, hi, lo);
        uint32_t off = SWZ128((uint32_t)((mb + g) * 128 + n0 * 2));
        *(uint32_t*)(smb + SM_A2HI + off) = hi;
        *(uint32_t*)(smb + SM_A2LO + off) = lo;
        split_pack(v2, v3, hi, lo);
        off = SWZ128((uint32_t)((mb + 8 + g) * 128 + n0 * 2));
        *(uint32_t*)(smb + SM_A2HI + off) = hi;
        *(uint32_t*)(smb + SM_A2LO + off) = lo;
    }
    __syncthreads();

    // ================= stage 2: 4 chunks of 144 kern rows =================
    const int px  = tid & 127, chh = tid >> 7;     // epilogue mapping
    const int erp = px >> 5, ecol = px & 31;
    const float* kr = (const float*)(smb + SM_KERN) + px * KSTRIDE_W;

    #pragma unroll 1
    for (int nc = 0; nc < 4; ++nc) {
        // ---- stage B2 chunk = w2 rows [nc*144 .. +144), bf16 hi/lo ----
        #pragma unroll
        for (int t = 0; t < 18; ++t) {
            int p = tid + 256 * t;                 // 4608 pairs
            int row = p >> 5, kp = p & 31;
            float2 v = *(const float2*)(w2 + (size_t)(nc * 144 + row) * 64 + kp * 2);
            uint32_t hi, lo; split_pack(v.x, v.y, hi, lo);
            uint32_t off = SWZ128((uint32_t)(row * 128 + kp * 4));
            *(uint32_t*)(smb + SM_B2HI + off) = hi;
            *(uint32_t*)(smb + SM_B2LO + off) = lo;
        }
        __syncthreads();   // B2 staged; also: prior epilogue done before kern overwrite

        // ---- MMA: kern_chunk[128px][144] = A2 * B2^T ----
        #pragma unroll
        for (int i = 0; i < 72; ++i) acc[i] = 0.0f;
        #pragma unroll
        for (int kk = 0; kk < 4; ++kk) {
            uint32_t Ah[4], Al[4];
            ldsm_x4(Ah, su + SM_A2HI + aoff + aswz[kk]);
            ldsm_x4(Al, su + SM_A2LO + aoff + aswz[kk]);
            #pragma unroll
            for (int nt = 0; nt < 18; ++nt) {
                uint32_t Bh[2], Bl[2];
                ldsm_x2(Bh, su + SM_B2HI + nt * 1024 + boff + bswz[kk]);
                ldsm_x2(Bl, su + SM_B2LO + nt * 1024 + boff + bswz[kk]);
                mma_bf16(acc + nt * 4, Ah, Bh);
                mma_bf16(acc + nt * 4, Al, Bh);
                mma_bf16(acc + nt * 4, Ah, Bl);
            }
        }
        // ---- C frags -> kern smem [px][n] ----
        #pragma unroll
        for (int nt = 0; nt < 18; ++nt) {
            int n0 = nt * 8 + q * 2;
            float2 u0; u0.x = acc[nt * 4 + 0]; u0.y = acc[nt * 4 + 1];
            float2 u1; u1.x = acc[nt * 4 + 2]; u1.y = acc[nt * 4 + 3];
            *(float2*)(smb + SM_KERN + (mb + g) * 600 + n0 * 4)     = u0;
            *(float2*)(smb + SM_KERN + (mb + 8 + g) * 600 + n0 * 4) = u1;
        }
        __syncthreads();   // kern complete

        // ---- epilogue: out[c,px] = sum_{i,j} kern[px][cl*9+i*3+j] * tap ----
        // pixel ecol's taps (j=0..2) live at halo s = 3 + ecol + j
        #pragma unroll
        for (int i8 = 0; i8 < 8; ++i8) {
            int cl = chh * 8 + i8;                 // local channel 0..15
            int c  = nc * 16 + cl;
            const float* kc = kr + cl * 9;
            const float* tb = sm + 256 + c * 240 + erp * 40 + ecol + 3;
            float s = 0.0f;
            #pragma unroll
            for (int i = 0; i < 3; ++i) {
                const float* rr2 = tb + i * 40;
                s = fmaf(kc[i * 3 + 0], rr2[0], s);
                s = fmaf(kc[i * 3 + 1], rr2[1], s);
                s = fmaf(kc[i * 3 + 2], rr2[2], s);
            }
            out[((size_t)(b * 64 + c) * 224 + (h0 + erp)) * 224 + w0c + ecol] = s;
        }
    }
}

extern "C" void kernel_launch(void* const* d_in, const int* in_sizes, int n_in,
                              void* d_out, int out_size)
{
    const float* x  = (const float*)d_in[0];   // (4,64,224,224)
    const float* w1 = (const float*)d_in[1];   // (64,64)
    const float* w2 = (const float*)d_in[2];   // (576,64)
    float* out = (float*)d_out;                // (4,64,224,224)

    cudaFuncSetAttribute(invol_mma_kernel,
                         cudaFuncAttributeMaxDynamicSharedMemorySize, SM_TOTAL);
    dim3 grid(224 / 32, 224 / 4, 4);           // 7 x 56 x 4 = 1568 blocks
    invol_mma_kernel<<<grid, 256, SM_TOTAL>>>(x, w1, w2, out);
}

// round 17
// speedup vs baseline: 1.8463x; 1.6436x over previous
#include <cuda_runtime.h>
#include <cuda_bf16.h>
#include <cstdint>

// ---------- warp-level bf16 MMA (plain PTX, works at compute_103) ----------
__device__ __forceinline__ void mma_bf16(float* c, const uint32_t* a, const uint32_t* b){
    asm volatile("mma.sync.aligned.m16n8k16.row.col.f32.bf16.bf16.f32 "
        "{%0,%1,%2,%3},{%4,%5,%6,%7},{%8,%9},{%0,%1,%2,%3};"
        : "+f"(c[0]), "+f"(c[1]), "+f"(c[2]), "+f"(c[3])
        : "r"(a[0]), "r"(a[1]), "r"(a[2]), "r"(a[3]), "r"(b[0]), "r"(b[1]));
}
__device__ __forceinline__ void ldsm_x4(uint32_t* r, uint32_t a){
    asm volatile("ldmatrix.sync.aligned.m8n8.x4.shared.b16 {%0,%1,%2,%3},[%4];"
        : "=r"(r[0]), "=r"(r[1]), "=r"(r[2]), "=r"(r[3]) : "r"(a));
}
__device__ __forceinline__ void ldsm_x2(uint32_t* r, uint32_t a){
    asm volatile("ldmatrix.sync.aligned.m8n8.x2.shared.b16 {%0,%1},[%2];"
        : "=r"(r[0]), "=r"(r[1]) : "r"(a));
}
#define SWZ128(off) ((off) ^ (((off) >> 3) & 0x70))

__device__ __forceinline__ void split_pack(float v0, float v1, uint32_t& hi, uint32_t& lo){
    __nv_bfloat16 h0 = __float2bfloat16_rn(v0), h1 = __float2bfloat16_rn(v1);
    __nv_bfloat16 l0 = __float2bfloat16_rn(v0 - __bfloat162float(h0));
    __nv_bfloat16 l1 = __float2bfloat16_rn(v1 - __bfloat162float(h1));
    hi = (uint32_t)__bfloat16_as_ushort(h0) | ((uint32_t)__bfloat16_as_ushort(h1) << 16);
    lo = (uint32_t)__bfloat16_as_ushort(l0) | ((uint32_t)__bfloat16_as_ushort(l1) << 16);
}

// ---------------- smem layout (bytes) ----------------
// xs halo @0: 64c x 6r x 38f (c-stride 228f = 912B)        = 58368
// stage1:  A1hi @58368 (16KB), A1lo @74752, B1hi @91136 (8KB), B1lo @99328
// stage2 (overlays stage1): B2hi @58368 (9216), B2lo @67584,
//          kern @76800: 128px x 74 f32 = 37888  -> end 114688
#define SM_A1HI  58368
#define SM_A1LO  74752
#define SM_B1HI  91136
#define SM_B1LO  99328
#define SM_B2HI  58368
#define SM_B2LO  67584
#define SM_KERN  76800
#define SM_TOTAL 114688
#define KSTR     74          // kern row stride (words), even for float2 stores

__global__ void __launch_bounds__(256, 2)
invol_mma2_kernel(const float* __restrict__ x, const float* __restrict__ w1,
                  const float* __restrict__ w2, float* __restrict__ out)
{
    extern __shared__ float sm[];
    char* smb = (char*)sm;
    uint32_t su;
    asm("{ .reg .u64 t; cvta.to.shared.u64 t, %1; cvt.u32.u64 %0, t; }" : "=r"(su) : "l"(smb));

    const int tid = threadIdx.x;
    const int L   = tid & 31;
    const int wid = tid >> 5;            // 8 warps
    const int w0c = blockIdx.x * 32;
    const int h0  = blockIdx.y * 4;
    const int b   = blockIdx.z;

    // ---------------- halo: 64c x 6r x 34col (xs stride 38) ----------------
    const float* xb = x + (size_t)b * 64 * 224 * 224;
    for (int rr = wid; rr < 384; rr += 8) {
        int c = rr / 6, r = rr - 6 * c;
        int gr = h0 - 1 + r;
        bool rok = ((unsigned)gr < 224u);
        const float* src = xb + ((size_t)c * 224 + gr) * 224;
        float* dst = sm + c * 228 + r * 38 + 3;
        #pragma unroll
        for (int ii = 0; ii < 2; ++ii) {
            int i = L + 32 * ii;
            if (i < 34) {
                int g = w0c - 1 + i;
                dst[i] = (rok && (unsigned)g < 224u) ? __ldg(src + g) : 0.0f;
            }
        }
    }

    // ---------------- B1 = w1 bf16 hi/lo (64 rows x 64 k, swizzled) --------
    #pragma unroll
    for (int t = 0; t < 8; ++t) {
        int p = tid + 256 * t;
        int row = p >> 5, kp = p & 31;
        float2 v = *(const float2*)(w1 + row * 64 + kp * 2);
        uint32_t hi, lo; split_pack(v.x, v.y, hi, lo);
        uint32_t off = SWZ128((uint32_t)(row * 128 + kp * 4));
        *(uint32_t*)(smb + SM_B1HI + off) = hi;
        *(uint32_t*)(smb + SM_B1LO + off) = lo;
    }
    __syncthreads();    // halo complete before xs reads below

    // ---------------- A1[px][c] from halo center ----------------
    {
        int px = tid >> 1, ch0 = (tid & 1) * 32;
        int rp = px >> 5, col = px & 31;
        const float* base = sm + (rp + 1) * 38 + 4 + col;   // + c*228
        #pragma unroll
        for (int cc = 0; cc < 16; ++cc) {
            int c = ch0 + 2 * cc;
            float v0 = base[c * 228], v1 = base[(c + 1) * 228];
            uint32_t hi, lo; split_pack(v0, v1, hi, lo);
            uint32_t off = SWZ128((uint32_t)(px * 128 + c * 2));
            *(uint32_t*)(smb + SM_A1HI + off) = hi;
            *(uint32_t*)(smb + SM_A1LO + off) = lo;
        }
    }
    __syncthreads();

    // ---------------- per-lane ldmatrix address components ------------------
    const int mb = wid * 16;
    const int arow = mb + (L & 7) + ((L & 8) ? 8 : 0);
    const uint32_t aoff = (uint32_t)(arow * 128);
    const int ars = arow & 7, akh = (L >> 4) & 1;
    const int lr = L & 7, bkb = (L >> 3) & 1;
    const uint32_t boff = (uint32_t)(lr * 128);
    uint32_t aswz[4], bswz[4];
    #pragma unroll
    for (int kk = 0; kk < 4; ++kk) {
        aswz[kk] = (uint32_t)(((2 * kk + akh) ^ ars) << 4);
        bswz[kk] = (uint32_t)(((2 * kk + bkb) ^ lr) << 4);
    }
    const int g = L >> 2, q = L & 3;

    // ================= stage 1: h = relu(X * w1^T), N=64 =================
    float acc1[32];
    #pragma unroll
    for (int i = 0; i < 32; ++i) acc1[i] = 0.0f;
    #pragma unroll
    for (int kk = 0; kk < 4; ++kk) {
        uint32_t A1h[4], A1l[4];
        ldsm_x4(A1h, su + SM_A1HI + aoff + aswz[kk]);
        ldsm_x4(A1l, su + SM_A1LO + aoff + aswz[kk]);
        #pragma unroll
        for (int nt = 0; nt < 8; ++nt) {
            uint32_t Bh[2], Bl[2];
            ldsm_x2(Bh, su + SM_B1HI + nt * 1024 + boff + bswz[kk]);
            ldsm_x2(Bl, su + SM_B1LO + nt * 1024 + boff + bswz[kk]);
            mma_bf16(acc1 + nt * 4, A1h, Bh);
            mma_bf16(acc1 + nt * 4, A1l, Bh);
            mma_bf16(acc1 + nt * 4, A1h, Bl);
        }
    }

    // ---- C1 frags ARE the A2 frags: relu + split, all in registers ----
    // A-frag kk: [ (g,k-lo), (g+8,k-lo), (g,k-hi), (g+8,k-hi) ]
    //          = C1 tiles nt=2kk (regs 8kk+0..3) and nt=2kk+1 (8kk+4..7)
    uint32_t Ah[4][4], Al[4][4];
    #pragma unroll
    for (int kk = 0; kk < 4; ++kk)
        #pragma unroll
        for (int j = 0; j < 4; ++j)
            split_pack(fmaxf(acc1[8 * kk + 2 * j], 0.0f),
                       fmaxf(acc1[8 * kk + 2 * j + 1], 0.0f),
                       Ah[kk][j], Al[kk][j]);
    __syncthreads();    // all A1/B1 ldsm complete before B2 overwrites region

    // ================= stage 2: 8 chunks of 72 kern rows (8 ch) ============
    const int px2 = tid & 127, half = tid >> 7;
    const int erp = px2 >> 5, ecol = px2 & 31;

    #pragma unroll 1
    for (int nc = 0; nc < 8; ++nc) {
        // ---- stage B2 chunk = w2 rows [nc*72 .. +72), bf16 hi/lo ----
        #pragma unroll
        for (int t = 0; t < 9; ++t) {
            int p = tid + 256 * t;                 // 2304 pairs
            int row = p >> 5, kp = p & 31;
            float2 v = *(const float2*)(w2 + (size_t)(nc * 72 + row) * 64 + kp * 2);
            uint32_t hi, lo; split_pack(v.x, v.y, hi, lo);
            uint32_t off = SWZ128((uint32_t)(row * 128 + kp * 4));
            *(uint32_t*)(smb + SM_B2HI + off) = hi;
            *(uint32_t*)(smb + SM_B2LO + off) = lo;
        }
        __syncthreads();   // B2 ready; also orders prev epilogue reads before kern writes

        // ---- MMA: kern_chunk[128px][72] = A2 * B2^T (A from registers) ----
        float acc[36];
        #pragma unroll
        for (int i = 0; i < 36; ++i) acc[i] = 0.0f;
        #pragma unroll
        for (int kk = 0; kk < 4; ++kk) {
            #pragma unroll
            for (int nt = 0; nt < 9; ++nt) {
                uint32_t Bh[2], Bl[2];
                ldsm_x2(Bh, su + SM_B2HI + nt * 1024 + boff + bswz[kk]);
                ldsm_x2(Bl, su + SM_B2LO + nt * 1024 + boff + bswz[kk]);
                mma_bf16(acc + nt * 4, Ah[kk], Bh);
                mma_bf16(acc + nt * 4, Al[kk], Bh);
                mma_bf16(acc + nt * 4, Ah[kk], Bl);
            }
        }
        // ---- C frags -> kern smem [px][n'] ----
        #pragma unroll
        for (int nt = 0; nt < 9; ++nt) {
            int n0 = nt * 8 + q * 2;
            float2 u0; u0.x = acc[nt * 4 + 0]; u0.y = acc[nt * 4 + 1];
            float2 u1; u1.x = acc[nt * 4 + 2]; u1.y = acc[nt * 4 + 3];
            *(float2*)(smb + SM_KERN + ((mb + g) * KSTR + n0) * 4)     = u0;
            *(float2*)(smb + SM_KERN + ((mb + 8 + g) * KSTR + n0) * 4) = u1;
        }
        __syncthreads();   // kern complete

        // ---- epilogue: 8 channels; thread -> (half: 4 ch) x (px2) ----
        const float* kr = (const float*)(smb + SM_KERN) + px2 * KSTR + half * 36;
        #pragma unroll
        for (int cl = 0; cl < 4; ++cl) {
            int c = nc * 8 + half * 4 + cl;
            const float* kc = kr + cl * 9;
            const float* tb = sm + c * 228 + erp * 38 + ecol + 3;
            float s = 0.0f;
            #pragma unroll
            for (int i = 0; i < 3; ++i) {
                const float* rr2 = tb + i * 38;
                s = fmaf(kc[i * 3 + 0], rr2[0], s);
                s = fmaf(kc[i * 3 + 1], rr2[1], s);
                s = fmaf(kc[i * 3 + 2], rr2[2], s);
            }
            out[((size_t)(b * 64 + c) * 224 + (h0 + erp)) * 224 + w0c + ecol] = s;
        }
        // no barrier needed here: next chunk's post-staging barrier orders
        // these kern reads before the next kern writes.
    }
}

extern "C" void kernel_launch(void* const* d_in, const int* in_sizes, int n_in,
                              void* d_out, int out_size)
{
    const float* x  = (const float*)d_in[0];   // (4,64,224,224)
    const float* w1 = (const float*)d_in[1];   // (64,64)
    const float* w2 = (const float*)d_in[2];   // (576,64)
    float* out = (float*)d_out;                // (4,64,224,224)

    cudaFuncSetAttribute(invol_mma2_kernel,
                         cudaFuncAttributeMaxDynamicSharedMemorySize, SM_TOTAL);
    dim3 grid(224 / 32, 224 / 4, 4);           // 7 x 56 x 4 = 1568 blocks
    invol_mma2_kernel<<<grid, 256, SM_TOTAL>>>(x, w1, w2, out);
}